// round 10
// baseline (speedup 1.0000x reference)
#include <cuda_runtime.h>
#include <cuda_bf16.h>
#include <cstdint>
#include <cstddef>

#define CH   128
#define HH   96
#define WW   96
#define HW   9216          // 96*96
#define BATCH 16
#define NOUT 1000

// Padded mixed layout: data pixel (h,w) -> plane[(h+1)*PP + (w+2)]
// border cells (rows 0,97,98,99; cols 0,1,98,99) are zero -> maskless gather.
#define PP    104
#define PPH   100
#define PLANE (PP * PPH)   // 10400 floats per (b,c) plane

// ---------------------------------------------------------------------------
// Scratch (device globals — no runtime allocation allowed)
// ---------------------------------------------------------------------------
__device__ float g_mixed[(size_t)BATCH * CH * PLANE];   // 85.2 MB (padded)
__device__ float g_x[(size_t)BATCH * CH * HW];          // 75.5 MB
__device__ float g_pool[BATCH * CH];
// bf16 pair-packed B operand: row r = b*64 + k2 holds u32(bf16 ch 2k2, 2k2+1)
__device__ unsigned int g_pbh[(size_t)BATCH * 64 * HW];
__device__ unsigned int g_pbl[(size_t)BATCH * 64 * HW];
// A fragments in mma register order: [slot][kstep(8)][mtile(8)][lane(32)]
__device__ uint4 g_afh[5 * 8 * 8 * 32];
__device__ uint4 g_afl[5 * 8 * 8 * 32];

// ---------------------------------------------------------------------------
__device__ __forceinline__ unsigned short bfbits(float x) {
    return __bfloat16_as_ushort(__float2bfloat16_rn(x));
}
__device__ __forceinline__ float bfval(float x) {
    return __bfloat162float(__float2bfloat16_rn(x));
}
__device__ __forceinline__ unsigned int pack2(unsigned short lo, unsigned short hi) {
    return (unsigned int)lo | ((unsigned int)hi << 16);
}
__device__ __forceinline__ void mma_bf16(float* d, uint4 a,
                                         unsigned int b0, unsigned int b1) {
    asm volatile(
        "mma.sync.aligned.m16n8k16.row.col.f32.bf16.bf16.f32 "
        "{%0,%1,%2,%3}, {%4,%5,%6,%7}, {%8,%9}, {%0,%1,%2,%3};"
        : "+f"(d[0]), "+f"(d[1]), "+f"(d[2]), "+f"(d[3])
        : "r"(a.x), "r"(a.y), "r"(a.z), "r"(a.w), "r"(b0), "r"(b1));
}

// ---------------------------------------------------------------------------
// prep_all: pack all 5 lin matrices into mma A-fragments (hi/lo bf16) in a
// single launch; also zeroes the pool accumulators.
// Thread map: t<1024 -> slot 0 (K=64); else 2048 threads per slot 1..4.
// ---------------------------------------------------------------------------
__global__ void prep_all(const float* __restrict__ in_lin,
                         const float* __restrict__ lay_lin,
                         float* __restrict__ pool) {
    int t = blockIdx.x * 256 + threadIdx.x;
    if (t < BATCH * CH) pool[t] = 0.f;

    const float* lin;
    int slot, K, local;
    if (t < 1024) {
        slot = 0; K = 64; local = t; lin = in_lin;
    } else if (t < 1024 + 4 * 2048) {
        int j = t - 1024;
        slot = 1 + j / 2048; K = 128; local = j & 2047;
        lin = lay_lin + (size_t)(slot - 1) * CH * CH;
    } else return;

    int lane  = local & 31;
    int mtile = (local >> 5) & 7;
    int ks    = local >> 8;
    int m0 = mtile * 16 + (lane >> 2);
    int k0 = ks * 16 + (lane & 3) * 2;

    float a00 = lin[(size_t)m0 * K + k0],           a01 = lin[(size_t)m0 * K + k0 + 1];
    float a10 = lin[(size_t)(m0 + 8) * K + k0],     a11 = lin[(size_t)(m0 + 8) * K + k0 + 1];
    float a02 = lin[(size_t)m0 * K + k0 + 8],       a03 = lin[(size_t)m0 * K + k0 + 9];
    float a12 = lin[(size_t)(m0 + 8) * K + k0 + 8], a13 = lin[(size_t)(m0 + 8) * K + k0 + 9];

    uint4 h, l;
    h.x = pack2(bfbits(a00), bfbits(a01));
    h.y = pack2(bfbits(a10), bfbits(a11));
    h.z = pack2(bfbits(a02), bfbits(a03));
    h.w = pack2(bfbits(a12), bfbits(a13));
    l.x = pack2(bfbits(a00 - bfval(a00)), bfbits(a01 - bfval(a01)));
    l.y = pack2(bfbits(a10 - bfval(a10)), bfbits(a11 - bfval(a11)));
    l.z = pack2(bfbits(a02 - bfval(a02)), bfbits(a03 - bfval(a03)));
    l.w = pack2(bfbits(a12 - bfval(a12)), bfbits(a13 - bfval(a13)));

    int off = ((slot * 8 + ks) * 8 + mtile) * 32 + lane;
    g_afh[off] = h;
    g_afl[off] = l;
}

// ---------------------------------------------------------------------------
// border_init: zero the guard border of every padded mixed plane.
// GEMM only ever writes the interior, so borders stay zero within a launch.
// ---------------------------------------------------------------------------
__global__ void border_init(float* __restrict__ m) {
    float* pl = m + (size_t)blockIdx.x * PLANE;
    for (int i = threadIdx.x; i < 4 * PP + 4 * 96; i += 128) {
        int idx;
        if (i < 4 * PP) {
            int r4 = i / PP;                       // 0..3
            int rr = (r4 == 0) ? 0 : (96 + r4);    // rows 0,97,98,99
            idx = rr * PP + (i - r4 * PP);
        } else {
            int j  = i - 4 * PP;
            int c4 = j / 96;                       // 0..3
            int col = (c4 < 2) ? c4 : (96 + c4);   // cols 0,1,98,99
            idx = (1 + (j - c4 * 96)) * PP + col;  // rows 1..96
        }
        pl[idx] = 0.f;
    }
}

// ---------------------------------------------------------------------------
// convert_in: x fp32 [16,64,HW] -> pair-packed bf16 hi/lo
// ---------------------------------------------------------------------------
__global__ void convert_in(const float* __restrict__ x,
                           unsigned int* __restrict__ pbh,
                           unsigned int* __restrict__ pbl) {
    size_t t = (size_t)blockIdx.x * 256 + threadIdx.x;
    int p4 = (int)(t % 2304);
    int k2 = (int)((t / 2304) % 32);
    int b  = (int)(t / (2304 * 32));
    const float4 v0 = *(const float4*)(x + ((size_t)b * 64 + 2 * k2)     * HW + p4 * 4);
    const float4 v1 = *(const float4*)(x + ((size_t)b * 64 + 2 * k2 + 1) * HW + p4 * 4);
    uint4 h, l;
    h.x = pack2(bfbits(v0.x), bfbits(v1.x));
    h.y = pack2(bfbits(v0.y), bfbits(v1.y));
    h.z = pack2(bfbits(v0.z), bfbits(v1.z));
    h.w = pack2(bfbits(v0.w), bfbits(v1.w));
    l.x = pack2(bfbits(v0.x - bfval(v0.x)), bfbits(v1.x - bfval(v1.x)));
    l.y = pack2(bfbits(v0.y - bfval(v0.y)), bfbits(v1.y - bfval(v1.y)));
    l.z = pack2(bfbits(v0.z - bfval(v0.z)), bfbits(v1.z - bfval(v1.z)));
    l.w = pack2(bfbits(v0.w - bfval(v0.w)), bfbits(v1.w - bfval(v1.w)));
    size_t o = ((size_t)b * 32 + k2) * HW + (size_t)p4 * 4;
    *(uint4*)(pbh + o) = h;
    *(uint4*)(pbl + o) = l;
}

// ---------------------------------------------------------------------------
// Tensor GEMM -> writes padded mixed planes.
// ---------------------------------------------------------------------------
#define BPITCH 136
template<int K>
__global__ __launch_bounds__(256, 2)
void mix_gemm_mma(const unsigned int* __restrict__ pbh,
                  const unsigned int* __restrict__ pbl,
                  float* __restrict__ outp, int slot) {
    constexpr int K2 = K / 2;
    constexpr int KS = K / 16;
    extern __shared__ unsigned int smb[];
    unsigned int* Bh = smb;
    unsigned int* Bl = smb + K2 * BPITCH;

    const int b     = blockIdx.y;
    const int pbase = blockIdx.x * 128;
    const int tid   = threadIdx.x;
    const int lane  = tid & 31;
    const int warp  = tid >> 5;
    const int wm    = warp >> 2;
    const int wn    = warp & 3;

    {
        const unsigned int* gh = pbh + ((size_t)b * K2) * HW + pbase;
        const unsigned int* gl = pbl + ((size_t)b * K2) * HW + pbase;
        for (int i = tid; i < K2 * 128; i += 256) {
            int r = i >> 7, c2 = i & 127;
            Bh[r * BPITCH + c2] = gh[(size_t)r * HW + c2];
            Bl[r * BPITCH + c2] = gl[(size_t)r * HW + c2];
        }
    }
    __syncthreads();

    float acc[4][4][4];
#pragma unroll
    for (int t = 0; t < 4; t++)
#pragma unroll
        for (int u = 0; u < 4; u++)
#pragma unroll
            for (int r = 0; r < 4; r++) acc[t][u][r] = 0.f;

    const uint4* afh = g_afh + (size_t)slot * 8 * 8 * 32;
    const uint4* afl = g_afl + (size_t)slot * 8 * 8 * 32;

#pragma unroll
    for (int ks = 0; ks < KS; ks++) {
        unsigned int bh0[4], bh1[4], bl0[4], bl1[4];
        const int r0 = (ks * 8 + (lane & 3)) * BPITCH;
        const int r1 = r0 + 4 * BPITCH;
#pragma unroll
        for (int u = 0; u < 4; u++) {
            int n = wn * 32 + u * 8 + (lane >> 2);
            bh0[u] = Bh[r0 + n]; bh1[u] = Bh[r1 + n];
            bl0[u] = Bl[r0 + n]; bl1[u] = Bl[r1 + n];
        }
#pragma unroll
        for (int t = 0; t < 4; t++) {
            uint4 ah = afh[(ks * 8 + wm * 4 + t) * 32 + lane];
            uint4 al = afl[(ks * 8 + wm * 4 + t) * 32 + lane];
#pragma unroll
            for (int u = 0; u < 4; u++) {
                mma_bf16(acc[t][u], ah, bh0[u], bh1[u]);
                mma_bf16(acc[t][u], ah, bl0[u], bl1[u]);
                mma_bf16(acc[t][u], al, bh0[u], bh1[u]);
            }
        }
    }

    float* mb = outp + (size_t)b * CH * PLANE;
#pragma unroll
    for (int t = 0; t < 4; t++) {
        int m0 = wm * 64 + t * 16 + (lane >> 2);
#pragma unroll
        for (int u = 0; u < 4; u++) {
            int p = pbase + wn * 32 + u * 8 + (lane & 3) * 2;
            int h = p / 96;
            int w = p - h * 96;
            size_t po = (size_t)(h + 1) * PP + (w + 2);
            *(float2*)(mb + (size_t)m0 * PLANE + po)       = make_float2(acc[t][u][0], acc[t][u][1]);
            *(float2*)(mb + (size_t)(m0 + 8) * PLANE + po) = make_float2(acc[t][u][2], acc[t][u][3]);
        }
    }
}

// ---------------------------------------------------------------------------
// Sample from padded mixed: maskless 4-tap gather (one coord clamp, zero
// border supplies out-of-range zeros), analytic box weight, residual add,
// optional bf16 emit for next GEMM, optional fused avg-pool accumulation.
// grid: (36, CH, BATCH), 256 threads.
// ---------------------------------------------------------------------------
__global__ void sample_kernel(const float* __restrict__ mixedp,
                              const float* __restrict__ geo,
                              const float* __restrict__ box,
                              const float* __restrict__ resid,
                              float* __restrict__ out,
                              unsigned int* __restrict__ pbh,
                              unsigned int* __restrict__ pbl,
                              int do_pool,
                              float* __restrict__ pool) {
    const int c = blockIdx.y;
    const int b = blockIdx.z;
    const int p = blockIdx.x * 256 + threadIdx.x;
    const int h = p / WW;
    const int w = p - h * WW;

    const float gxc = (w + 0.5f) * (2.0f / WW) - 1.0f;
    const float gyc = (h + 0.5f) * (2.0f / HH) - 1.0f;

    const float* g = geo + c * 6;
    float ix = (__ldg(g + 0) * gxc + __ldg(g + 1) * gyc + __ldg(g + 2)) * 48.f + 47.5f;
    float iy = (__ldg(g + 3) * gxc + __ldg(g + 4) * gyc + __ldg(g + 5)) * 48.f + 47.5f;
    // single clamp; borders hold zeros so taps need no masks
    ix = fminf(fmaxf(ix, -1.0f), 96.0f);
    iy = fminf(fmaxf(iy, -1.0f), 96.0f);
    float fx0 = floorf(ix), fy0 = floorf(iy);
    int   x0 = (int)fx0, y0 = (int)fy0;
    float wx1 = ix - fx0, wy1 = iy - fy0;
    float wx0 = 1.0f - wx1, wy0 = 1.0f - wy1;

    const float* tapb = mixedp + ((size_t)b * CH + c) * PLANE
                      + (size_t)(y0 + 1) * PP + (x0 + 2);
    float t00 = tapb[0],  t01 = tapb[1];
    float t10 = tapb[PP], t11 = tapb[PP + 1];
    float s = wy0 * fmaf(wx0, t00, wx1 * t01)
            + wy1 * fmaf(wx0, t10, wx1 * t11);

    // box weight (sample of ones): separable masked sums, no loads
    const float* bx = box + c * 6;
    float bix = (__ldg(bx + 0) * gxc + __ldg(bx + 1) * gyc + __ldg(bx + 2)) * 48.f + 47.5f;
    float biy = (__ldg(bx + 3) * gxc + __ldg(bx + 4) * gyc + __ldg(bx + 5)) * 48.f + 47.5f;
    float bfx0 = floorf(bix), bfy0 = floorf(biy);
    int   bx0 = (int)bfx0, by0 = (int)bfy0;
    float bwx1 = bix - bfx0, bwy1 = biy - bfy0;
    float sx = (((unsigned)bx0       < (unsigned)WW) ? (1.f - bwx1) : 0.f)
             + (((unsigned)(bx0 + 1) < (unsigned)WW) ? bwx1         : 0.f);
    float sy = (((unsigned)by0       < (unsigned)HH) ? (1.f - bwy1) : 0.f)
             + (((unsigned)(by0 + 1) < (unsigned)HH) ? bwy1         : 0.f);

    const size_t idx = ((size_t)b * CH + c) * HW + p;
    float v = s * (sx * sy);
    if (resid) v += resid[idx];
    out[idx] = v;

    if (pbh) {
        unsigned short hb = bfbits(v);
        unsigned short lb = bfbits(v - __bfloat162float(__ushort_as_bfloat16(hb)));
        size_t hwi = (((size_t)b * 64 + (c >> 1)) * HW + p) * 2 + (c & 1);
        ((unsigned short*)pbh)[hwi] = hb;
        ((unsigned short*)pbl)[hwi] = lb;
    }

    if (do_pool) {
        float r = v;
        for (int o = 16; o > 0; o >>= 1) r += __shfl_down_sync(0xffffffffu, r, o);
        __shared__ float sm[8];
        if ((threadIdx.x & 31) == 0) sm[threadIdx.x >> 5] = r;
        __syncthreads();
        if (threadIdx.x == 0) {
            float tt = 0.f;
            for (int i = 0; i < 8; i++) tt += sm[i];
            atomicAdd(pool + b * CH + c, tt);
        }
    }
}

// ---------------------------------------------------------------------------
// Dense head (pool holds plane sums; fold the 1/HW mean here).
// ---------------------------------------------------------------------------
__global__ void dense_kernel(const float* __restrict__ pooled,
                             const float* __restrict__ dw,
                             const float* __restrict__ db,
                             float* __restrict__ logits) {
    int gid = blockIdx.x * 256 + threadIdx.x;
    if (gid >= BATCH * NOUT) return;
    int o = gid % NOUT;
    int b = gid / NOUT;
    const float* pr = pooled + b * CH;
    const float* wr = dw + (size_t)o * CH;
    float s = 0.f;
#pragma unroll 16
    for (int c = 0; c < CH; c++) s = fmaf(pr[c], wr[c], s);
    logits[gid] = s * (1.0f / HW) + db[o];
}

// ---------------------------------------------------------------------------
extern "C" void kernel_launch(void* const* d_in, const int* in_sizes, int n_in,
                              void* d_out, int out_size) {
    const float* x       = (const float*)d_in[0];
    const float* in_geo  = (const float*)d_in[1];
    const float* in_box  = (const float*)d_in[2];
    const float* in_lin  = (const float*)d_in[3];
    const float* lay_geo = (const float*)d_in[4];
    const float* lay_box = (const float*)d_in[5];
    const float* lay_lin = (const float*)d_in[6];
    const float* dense_w = (const float*)d_in[7];
    const float* dense_b = (const float*)d_in[8];

    float* out    = (float*)d_out;
    float* logits = out;
    float* feat   = out + BATCH * NOUT;

    float *mixed_p, *x_p, *pool_p;
    unsigned int *pbh_p, *pbl_p;
    cudaGetSymbolAddress((void**)&mixed_p, g_mixed);
    cudaGetSymbolAddress((void**)&x_p,     g_x);
    cudaGetSymbolAddress((void**)&pool_p,  g_pool);
    cudaGetSymbolAddress((void**)&pbh_p,   g_pbh);
    cudaGetSymbolAddress((void**)&pbl_p,   g_pbl);

    const int smem64  = 2 * 32 * BPITCH * 4;   // 34816
    const int smem128 = 2 * 64 * BPITCH * 4;   // 69632
    static bool attr_done = false;
    if (!attr_done) {
        cudaFuncSetAttribute(mix_gemm_mma<64>,  cudaFuncAttributeMaxDynamicSharedMemorySize, smem64);
        cudaFuncSetAttribute(mix_gemm_mma<128>, cudaFuncAttributeMaxDynamicSharedMemorySize, smem128);
        attr_done = true;
    }

    // prep: A fragments + pool zero (1 launch), border zeros, input bf16
    prep_all<<<(1024 + 4 * 2048 + 255) / 256, 256>>>(in_lin, lay_lin, pool_p);
    border_init<<<BATCH * CH, 128>>>(mixed_p);
    convert_in<<<(BATCH * 32 * 2304 + 255) / 256, 256>>>(x, pbh_p, pbl_p);

    dim3 ggrid(HW / 128, BATCH);          // (72, 16)
    dim3 sgrid(HW / 256, CH, BATCH);      // (36, 128, 16)

    // input layer (K=64, no residual)
    mix_gemm_mma<64><<<ggrid, 256, smem64>>>(pbh_p, pbl_p, mixed_p, 0);
    sample_kernel<<<sgrid, 256>>>(mixed_p, in_geo, in_box, nullptr, x_p,
                                  pbh_p, pbl_p, 0, pool_p);

    // 4 residual layers (K=128)
    for (int i = 0; i < 4; i++) {
        mix_gemm_mma<128><<<ggrid, 256, smem128>>>(pbh_p, pbl_p, mixed_p, i + 1);
        bool last = (i == 3);
        float* dst = last ? feat : x_p;
        sample_kernel<<<sgrid, 256>>>(mixed_p, lay_geo + (size_t)i * CH * 6,
                                      lay_box + (size_t)i * CH * 6, x_p, dst,
                                      last ? nullptr : pbh_p,
                                      last ? nullptr : pbl_p,
                                      last ? 1 : 0, pool_p);
    }

    dense_kernel<<<(BATCH * NOUT + 255) / 256, 256>>>(pool_p, dense_w, dense_b, logits);
}